// round 5
// baseline (speedup 1.0000x reference)
#include <cuda_runtime.h>
#include <cuda_fp16.h>
#include <cstdint>

#define N_NODES 50000
#define N_EDGES 400000
#define D_IN    1024
#define D_HID   512
#define D_LAT   256

// Scratch (allocation-free rule: __device__ globals)
__device__ __half g_s1h[(size_t)N_NODES * D_HID];   // x @ W1 (fp16, scatter src)
__device__ float  g_h  [(size_t)N_NODES * D_HID];   // agg1 (f32, atomic dst)
__device__ __half g_s2h[(size_t)N_NODES * D_LAT];   // hh @ W2 (fp16, scatter src)
__device__ __half g_xh [(size_t)N_NODES * D_IN];    // x in fp16
__device__ __half g_hh [(size_t)N_NODES * D_HID];   // relu(h+b1) in fp16
__device__ __half g_w1t[(size_t)D_HID * D_IN];      // W1^T fp16 [N][K]
__device__ __half g_w2t[(size_t)D_LAT * D_HID];     // W2^T fp16 [N][K]

// ---------------------------------------------------------------------------
// fp16 mma.sync GEMM: C[M,N](f16) = A[M,K](f16) @ Bt[N,K](f16)^T
// CTA tile 128x256, BK=32, 3-stage cp.async, 512 thr (16 warps, warp 64x32).
// smem rows of 16 words, XOR swizzle word' = word ^ (((row>>1)&3)<<2).
// ---------------------------------------------------------------------------
#define BM 128
#define BN 256
#define BK 32
#define STAGES 3
#define A_WORDS (BM * 16)                 // uint32 words per A stage
#define B_WORDS (BN * 16)
#define STAGE_WORDS (A_WORDS + B_WORDS)   // 6144 words = 24KB
#define SMEM_BYTES (STAGES * STAGE_WORDS * 4)

__device__ __forceinline__ void hmma(float c[4], const uint32_t a[4], const uint32_t b[2]) {
    asm volatile(
        "mma.sync.aligned.m16n8k16.row.col.f32.f16.f16.f32 "
        "{%0,%1,%2,%3}, {%4,%5,%6,%7}, {%8,%9}, {%0,%1,%2,%3};"
        : "+f"(c[0]), "+f"(c[1]), "+f"(c[2]), "+f"(c[3])
        : "r"(a[0]), "r"(a[1]), "r"(a[2]), "r"(a[3]), "r"(b[0]), "r"(b[1]));
}

__device__ __forceinline__ void cp16(uint32_t dst, const void* src, int sz) {
    asm volatile("cp.async.ca.shared.global [%0], [%1], 16, %2;\n"
                 :: "r"(dst), "l"(src), "r"(sz));
}
__device__ __forceinline__ void cp16u(uint32_t dst, const void* src) {
    asm volatile("cp.async.ca.shared.global [%0], [%1], 16;\n"
                 :: "r"(dst), "l"(src));
}

__global__ __launch_bounds__(512, 1)
void gemm_h(const __half* __restrict__ A, const __half* __restrict__ Bt,
            __half* __restrict__ C, int M, int N, int K) {
    extern __shared__ uint32_t smem[];
    const uint32_t sbase = (uint32_t)__cvta_generic_to_shared(smem);

    const int tid  = threadIdx.x;
    const int lane = tid & 31;
    const int wid  = tid >> 5;
    const int warp_m = wid & 1;      // 2 warps along M (64 rows each)
    const int warp_n = wid >> 1;     // 8 warps along N (32 cols each)
    const int qr = lane >> 2;        // 0..7
    const int qc = lane & 3;         // 0..3
    const int brow = blockIdx.x * BM;
    const int bcol = blockIdx.y * BN;

    float acc[4][4][4];
    #pragma unroll
    for (int i = 0; i < 4; i++)
        #pragma unroll
        for (int j = 0; j < 4; j++)
            #pragma unroll
            for (int k = 0; k < 4; k++) acc[i][j][k] = 0.f;

    // async stage loader: A 128 rows x 4 chunks(16B), B 256 rows x 4 chunks
    auto load_stage = [&](int kt, int s) {
        const int kb = kt * BK;                          // in halfs
        const uint32_t ab = sbase + (uint32_t)(s * STAGE_WORDS) * 4;
        const uint32_t bb = ab + A_WORDS * 4;
        {                                                // A: 512 chunks
            int r = tid >> 2, c4 = tid & 3;
            int gr = brow + r;
            uint32_t dst = ab + r * 64 + ((c4 ^ ((r >> 1) & 3)) << 4);
            cp16(dst, A + (size_t)gr * K + kb + c4 * 8, (gr < M) ? 16 : 0);
        }
        #pragma unroll
        for (int t = 0; t < 2; t++) {                    // B: 1024 chunks
            int idx = tid + t * 512;
            int r = idx >> 2, c4 = idx & 3;
            uint32_t dst = bb + r * 64 + ((c4 ^ ((r >> 1) & 3)) << 4);
            cp16u(dst, Bt + (size_t)(bcol + r) * K + kb + c4 * 8);
        }
    };

    const int nk = K / BK;
    #pragma unroll
    for (int i = 0; i < STAGES - 1; i++) {
        load_stage(i, i);
        asm volatile("cp.async.commit_group;\n");
    }

    const int fA = ((qr >> 1) & 3) << 2;     // swizzle const (rows ≡ qr mod 8)
    const int rowA0 = warp_m * 64 + qr;
    const int rowB0 = warp_n * 32 + qr;

    for (int kt = 0; kt < nk; kt++) {
        asm volatile("cp.async.wait_group %0;\n" :: "n"(STAGES - 2));
        __syncthreads();

        if (kt + STAGES - 1 < nk) load_stage(kt + STAGES - 1, (kt + STAGES - 1) % STAGES);
        asm volatile("cp.async.commit_group;\n");

        const int s = kt % STAGES;
        const uint32_t* As = smem + s * STAGE_WORDS;
        const uint32_t* Bs = As + A_WORDS;

        #pragma unroll
        for (int ks = 0; ks < 2; ks++) {
            const int w0 = (ks * 8 + qc)     ^ fA;
            const int w1 = (ks * 8 + qc + 4) ^ fA;
            uint32_t a[4][4], b[4][2];
            #pragma unroll
            for (int mt = 0; mt < 4; mt++) {
                int r0 = (rowA0 + mt * 16) * 16;
                a[mt][0] = As[r0       + w0];
                a[mt][1] = As[r0 + 128 + w0];      // +8 rows * 16 words
                a[mt][2] = As[r0       + w1];
                a[mt][3] = As[r0 + 128 + w1];
            }
            #pragma unroll
            for (int nt = 0; nt < 4; nt++) {
                int r0 = (rowB0 + nt * 8) * 16;
                b[nt][0] = Bs[r0 + w0];
                b[nt][1] = Bs[r0 + w1];
            }
            #pragma unroll
            for (int mt = 0; mt < 4; mt++)
                #pragma unroll
                for (int nt = 0; nt < 4; nt++)
                    hmma(acc[mt][nt], a[mt], b[nt]);
        }
        __syncthreads();
    }

    // epilogue: fp16 pairs
    #pragma unroll
    for (int mt = 0; mt < 4; mt++) {
        int r = brow + warp_m * 64 + mt * 16 + qr;
        #pragma unroll
        for (int nt = 0; nt < 4; nt++) {
            int c = bcol + warp_n * 32 + nt * 8 + qc * 2;
            if (r < M) {
                __half2 h = __floats2half2_rn(acc[mt][nt][0], acc[mt][nt][1]);
                *(__half2*)(C + (size_t)r * N + c) = h;
            }
            if (r + 8 < M) {
                __half2 h = __floats2half2_rn(acc[mt][nt][2], acc[mt][nt][3]);
                *(__half2*)(C + (size_t)(r + 8) * N + c) = h;
            }
        }
    }
}

// ---------------------------------------------------------------------------
// f32 -> f16 convert (grid-stride, float4 -> 8B)
// ---------------------------------------------------------------------------
__global__ void to_half(const float4* __restrict__ in, uint2* __restrict__ out, int n4) {
    int i = blockIdx.x * blockDim.x + threadIdx.x;
    int stride = gridDim.x * blockDim.x;
    for (; i < n4; i += stride) {
        float4 v = in[i];
        __half2 h0 = __floats2half2_rn(v.x, v.y);
        __half2 h1 = __floats2half2_rn(v.z, v.w);
        out[i] = make_uint2(*(uint32_t*)&h0, *(uint32_t*)&h1);
    }
}

// ---------------------------------------------------------------------------
// transpose f32 -> f16: out[C][R] = (half)in[R][C]
// ---------------------------------------------------------------------------
__global__ __launch_bounds__(256)
void transpose_h(const float* __restrict__ in, __half* __restrict__ out, int R, int Cc) {
    __shared__ float t[32][33];
    const int c0 = blockIdx.x * 32, r0 = blockIdx.y * 32;
    const int tx = threadIdx.x, ty = threadIdx.y;
    #pragma unroll
    for (int i = ty; i < 32; i += 8)
        t[i][tx] = in[(size_t)(r0 + i) * Cc + c0 + tx];
    __syncthreads();
    #pragma unroll
    for (int i = ty; i < 32; i += 8)
        out[(size_t)(c0 + i) * R + r0 + tx] = __float2half(t[tx][i]);
}

// ---------------------------------------------------------------------------
// Scatter-add: out[dst] += (float)S[src] * w   (fp16 src, f32 RED atomics)
// ---------------------------------------------------------------------------
template<int D>
__global__ __launch_bounds__(256)
void scatter_add_h(const __half* __restrict__ S, const int* __restrict__ ei,
                   const float* __restrict__ ew, float* __restrict__ out) {
    constexpr int TPE = D / 4;        // threads per edge, 4 features each
    constexpr int EPB = 256 / TPE;
    const int e = blockIdx.x * EPB + threadIdx.x / TPE;
    if (e >= N_EDGES) return;
    const int j = threadIdx.x % TPE;
    const int src = ei[e];
    const int dst = ei[N_EDGES + e];
    const float w = ew[e];
    uint2 raw = ((const uint2*)(S + (size_t)src * D))[j];
    __half2 h0 = *(__half2*)&raw.x;
    __half2 h1 = *(__half2*)&raw.y;
    float2 f0 = __half22float2(h0);
    float2 f1 = __half22float2(h1);
    float4 v = make_float4(f0.x * w, f0.y * w, f1.x * w, f1.y * w);
    float* op = out + (size_t)dst * D + j * 4;
    asm volatile("red.global.add.v4.f32 [%0], {%1,%2,%3,%4};"
                 :: "l"(op), "f"(v.x), "f"(v.y), "f"(v.z), "f"(v.w) : "memory");
}

// ---------------------------------------------------------------------------
// bias+relu -> fp16 (feeds GEMM2)
// ---------------------------------------------------------------------------
template<int D>
__global__ void bias_relu_h(const float* __restrict__ p, const float* __restrict__ b,
                            uint2* __restrict__ out, int n4) {
    int i = blockIdx.x * blockDim.x + threadIdx.x;
    int stride = gridDim.x * blockDim.x;
    for (; i < n4; i += stride) {
        float4 v = ((const float4*)p)[i];
        float4 bb = ((const float4*)b)[i % (D / 4)];
        v.x = fmaxf(v.x + bb.x, 0.f);
        v.y = fmaxf(v.y + bb.y, 0.f);
        v.z = fmaxf(v.z + bb.z, 0.f);
        v.w = fmaxf(v.w + bb.w, 0.f);
        __half2 h0 = __floats2half2_rn(v.x, v.y);
        __half2 h1 = __floats2half2_rn(v.z, v.w);
        out[i] = make_uint2(*(uint32_t*)&h0, *(uint32_t*)&h1);
    }
}

// bias+relu in-place f32 (final output)
template<int D>
__global__ void bias_relu(float* __restrict__ p, const float* __restrict__ b, int n4) {
    int i = blockIdx.x * blockDim.x + threadIdx.x;
    int stride = gridDim.x * blockDim.x;
    for (; i < n4; i += stride) {
        float4 v = ((float4*)p)[i];
        float4 bb = ((const float4*)b)[i % (D / 4)];
        v.x = fmaxf(v.x + bb.x, 0.f);
        v.y = fmaxf(v.y + bb.y, 0.f);
        v.z = fmaxf(v.z + bb.z, 0.f);
        v.w = fmaxf(v.w + bb.w, 0.f);
        ((float4*)p)[i] = v;
    }
}

// ---------------------------------------------------------------------------
// launch
// ---------------------------------------------------------------------------
extern "C" void kernel_launch(void* const* d_in, const int* in_sizes, int n_in,
                              void* d_out, int out_size) {
    const float* x  = (const float*)d_in[0];
    const int*   ei = (const int*)  d_in[1];
    const float* ew = (const float*)d_in[2];
    const float* W1 = (const float*)d_in[3];
    const float* b1 = (const float*)d_in[4];
    const float* W2 = (const float*)d_in[5];
    const float* b2 = (const float*)d_in[6];
    float* out = (float*)d_out;

    float *h;
    __half *s1h, *s2h, *xh, *hh, *w1t, *w2t;
    cudaGetSymbolAddress((void**)&s1h, g_s1h);
    cudaGetSymbolAddress((void**)&h,   g_h);
    cudaGetSymbolAddress((void**)&s2h, g_s2h);
    cudaGetSymbolAddress((void**)&xh,  g_xh);
    cudaGetSymbolAddress((void**)&hh,  g_hh);
    cudaGetSymbolAddress((void**)&w1t, g_w1t);
    cudaGetSymbolAddress((void**)&w2t, g_w2t);

    static bool attr_set = false;
    if (!attr_set) {
        cudaFuncSetAttribute(gemm_h, cudaFuncAttributeMaxDynamicSharedMemorySize,
                             SMEM_BYTES);
        attr_set = true;
    }

    const int mblocks = (N_NODES + BM - 1) / BM;   // 391

    // fp16 staging
    to_half<<<4096, 256>>>((const float4*)x, (uint2*)xh, N_NODES * D_IN / 4);
    transpose_h<<<dim3(D_HID / 32, D_IN / 32), dim3(32, 8)>>>(W1, w1t, D_IN, D_HID);
    transpose_h<<<dim3(D_LAT / 32, D_HID / 32), dim3(32, 8)>>>(W2, w2t, D_HID, D_LAT);

    // Layer 1: s1h = x @ W1 ; h = scatter(s1h) ; hh = relu(h + b1) fp16
    gemm_h<<<dim3(mblocks, D_HID / BN), 512, SMEM_BYTES>>>(xh, w1t, s1h,
                                                           N_NODES, D_HID, D_IN);
    cudaMemsetAsync(h, 0, (size_t)N_NODES * D_HID * sizeof(float));
    scatter_add_h<D_HID><<<N_EDGES / (256 / (D_HID / 4)), 256>>>(s1h, ei, ew, h);
    bias_relu_h<D_HID><<<4096, 256>>>(h, b1, (uint2*)hh, N_NODES * D_HID / 4);

    // Layer 2: s2h = hh @ W2 ; out = relu(scatter(s2h) + b2)
    gemm_h<<<dim3(mblocks, D_LAT / BN), 512, SMEM_BYTES>>>(hh, w2t, s2h,
                                                           N_NODES, D_LAT, D_HID);
    cudaMemsetAsync(out, 0, (size_t)N_NODES * D_LAT * sizeof(float));
    scatter_add_h<D_LAT><<<N_EDGES / (256 / (D_LAT / 4)), 256>>>(s2h, ei, ew, out);
    bias_relu<D_LAT><<<4096, 256>>>(out, b2, N_NODES * D_LAT / 4);
}

// round 6
// speedup vs baseline: 1.0436x; 1.0436x over previous
#include <cuda_runtime.h>
#include <cuda_fp16.h>
#include <cstdint>

#define N_NODES 50000
#define N_EDGES 400000
#define D_IN    1024
#define D_HID   512
#define D_LAT   256

// Scratch (allocation-free rule: __device__ globals)
__device__ __half g_s1h[(size_t)N_NODES * D_HID];   // x @ W1 (fp16, scatter src)
__device__ float  g_h  [(size_t)N_NODES * D_HID];   // agg1 (f32, atomic dst)
__device__ __half g_s2h[(size_t)N_NODES * D_LAT];   // hh @ W2 (fp16, scatter src)
__device__ __half g_xh [(size_t)N_NODES * D_IN];    // x in fp16
__device__ __half g_hh [(size_t)N_NODES * D_HID];   // relu(h+b1) in fp16
__device__ __half g_w1t[(size_t)D_HID * D_IN];      // W1^T fp16 [N][K]
__device__ __half g_w2t[(size_t)D_LAT * D_HID];     // W2^T fp16 [N][K]

// ---------------------------------------------------------------------------
// fp16 mma.sync GEMM: C[M,N](f16) = A[M,K](f16) @ Bt[N,K](f16)^T
// CTA tile 128x256, BK=32, 3-stage cp.async, 512 thr (16 warps, warp 64x32).
// smem rows = 64B (4 x 16B chunks), swizzle chunk' = chunk ^ ((row>>1)&3).
// Fragments loaded via ldmatrix.x4 (conflict-free under this swizzle).
// ---------------------------------------------------------------------------
#define BM 128
#define BN 256
#define BK 32
#define STAGES 3
#define A_WORDS (BM * 16)                 // uint32 words per A stage
#define B_WORDS (BN * 16)
#define STAGE_WORDS (A_WORDS + B_WORDS)   // 6144 words = 24KB
#define SMEM_BYTES (STAGES * STAGE_WORDS * 4)

__device__ __forceinline__ void hmma(float c[4], const uint32_t a[4],
                                     uint32_t b0, uint32_t b1) {
    asm volatile(
        "mma.sync.aligned.m16n8k16.row.col.f32.f16.f16.f32 "
        "{%0,%1,%2,%3}, {%4,%5,%6,%7}, {%8,%9}, {%0,%1,%2,%3};"
        : "+f"(c[0]), "+f"(c[1]), "+f"(c[2]), "+f"(c[3])
        : "r"(a[0]), "r"(a[1]), "r"(a[2]), "r"(a[3]), "r"(b0), "r"(b1));
}

__device__ __forceinline__ void ldsm4(uint32_t r[4], uint32_t addr) {
    asm volatile("ldmatrix.sync.aligned.m8n8.x4.shared.b16 {%0,%1,%2,%3}, [%4];"
                 : "=r"(r[0]), "=r"(r[1]), "=r"(r[2]), "=r"(r[3]) : "r"(addr));
}

__device__ __forceinline__ void cp16(uint32_t dst, const void* src, int sz) {
    asm volatile("cp.async.ca.shared.global [%0], [%1], 16, %2;\n"
                 :: "r"(dst), "l"(src), "r"(sz));
}
__device__ __forceinline__ void cp16u(uint32_t dst, const void* src) {
    asm volatile("cp.async.ca.shared.global [%0], [%1], 16;\n"
                 :: "r"(dst), "l"(src));
}

__global__ __launch_bounds__(512, 1)
void gemm_h(const __half* __restrict__ A, const __half* __restrict__ Bt,
            __half* __restrict__ C, int M, int N, int K) {
    extern __shared__ uint32_t smem[];
    const uint32_t sbase = (uint32_t)__cvta_generic_to_shared(smem);

    const int tid  = threadIdx.x;
    const int lane = tid & 31;
    const int wid  = tid >> 5;
    const int warp_m = wid & 1;      // 2 warps along M (64 rows each)
    const int warp_n = wid >> 1;     // 8 warps along N (32 cols each)
    const int qr = lane >> 2;        // 0..7
    const int qc = lane & 3;         // 0..3
    const int brow = blockIdx.x * BM;
    const int bcol = blockIdx.y * BN;

    // ldmatrix per-lane geometry
    const int laneA_row = lane & 15;            // row within 16-row tile
    const int laneA_h   = lane >> 4;            // k8-half select
    const int laneB_row = (lane & 7) + ((lane >> 4) << 3);
    const int laneB_h   = (lane >> 3) & 1;
    const int rowA_base = warp_m * 64 + laneA_row;
    const int rowB_base = warp_n * 32 + laneB_row;

    float acc[4][4][4];
    #pragma unroll
    for (int i = 0; i < 4; i++)
        #pragma unroll
        for (int j = 0; j < 4; j++)
            #pragma unroll
            for (int k = 0; k < 4; k++) acc[i][j][k] = 0.f;

    // async stage loader: A 128 rows x 4 chunks(16B), B 256 rows x 4 chunks
    auto load_stage = [&](int kt, int s) {
        const int kb = kt * BK;                          // in halfs
        const uint32_t ab = sbase + (uint32_t)(s * STAGE_WORDS) * 4;
        const uint32_t bb = ab + A_WORDS * 4;
        {                                                // A: 512 chunks
            int r = tid >> 2, c4 = tid & 3;
            int gr = brow + r;
            uint32_t dst = ab + r * 64 + ((c4 ^ ((r >> 1) & 3)) << 4);
            cp16(dst, A + (size_t)gr * K + kb + c4 * 8, (gr < M) ? 16 : 0);
        }
        #pragma unroll
        for (int t = 0; t < 2; t++) {                    // B: 1024 chunks
            int idx = tid + t * 512;
            int r = idx >> 2, c4 = idx & 3;
            uint32_t dst = bb + r * 64 + ((c4 ^ ((r >> 1) & 3)) << 4);
            cp16u(dst, Bt + (size_t)(bcol + r) * K + kb + c4 * 8);
        }
    };

    const int nk = K / BK;
    #pragma unroll
    for (int i = 0; i < STAGES - 1; i++) {
        load_stage(i, i);
        asm volatile("cp.async.commit_group;\n");
    }

    for (int kt = 0; kt < nk; kt++) {
        asm volatile("cp.async.wait_group %0;\n" :: "n"(STAGES - 2));
        __syncthreads();

        if (kt + STAGES - 1 < nk) load_stage(kt + STAGES - 1, (kt + STAGES - 1) % STAGES);
        asm volatile("cp.async.commit_group;\n");

        const int s = kt % STAGES;
        const uint32_t Ab = sbase + (uint32_t)(s * STAGE_WORDS) * 4;
        const uint32_t Bb = Ab + A_WORDS * 4;

        #pragma unroll
        for (int ks = 0; ks < 2; ks++) {
            uint32_t a[4][4], b[2][4];
            #pragma unroll
            for (int mt = 0; mt < 4; mt++) {
                int row = rowA_base + mt * 16;
                uint32_t ad = Ab + row * 64 +
                    (((ks * 2 + laneA_h) ^ ((row >> 1) & 3)) << 4);
                ldsm4(a[mt], ad);
            }
            #pragma unroll
            for (int np = 0; np < 2; np++) {
                int row = rowB_base + np * 16;
                uint32_t bd = Bb + row * 64 +
                    (((ks * 2 + laneB_h) ^ ((row >> 1) & 3)) << 4);
                ldsm4(b[np], bd);
            }
            #pragma unroll
            for (int mt = 0; mt < 4; mt++)
                #pragma unroll
                for (int nt = 0; nt < 4; nt++)
                    hmma(acc[mt][nt], a[mt], b[nt >> 1][(nt & 1) * 2],
                                             b[nt >> 1][(nt & 1) * 2 + 1]);
        }
        __syncthreads();
    }

    // epilogue: fp16 pairs
    #pragma unroll
    for (int mt = 0; mt < 4; mt++) {
        int r = brow + warp_m * 64 + mt * 16 + qr;
        #pragma unroll
        for (int nt = 0; nt < 4; nt++) {
            int c = bcol + warp_n * 32 + nt * 8 + qc * 2;
            if (r < M) {
                __half2 h = __floats2half2_rn(acc[mt][nt][0], acc[mt][nt][1]);
                *(__half2*)(C + (size_t)r * N + c) = h;
            }
            if (r + 8 < M) {
                __half2 h = __floats2half2_rn(acc[mt][nt][2], acc[mt][nt][3]);
                *(__half2*)(C + (size_t)(r + 8) * N + c) = h;
            }
        }
    }
}

// ---------------------------------------------------------------------------
// f32 -> f16 convert (grid-stride, float4 -> 8B)
// ---------------------------------------------------------------------------
__global__ void to_half(const float4* __restrict__ in, uint2* __restrict__ out, int n4) {
    int i = blockIdx.x * blockDim.x + threadIdx.x;
    int stride = gridDim.x * blockDim.x;
    for (; i < n4; i += stride) {
        float4 v = in[i];
        __half2 h0 = __floats2half2_rn(v.x, v.y);
        __half2 h1 = __floats2half2_rn(v.z, v.w);
        out[i] = make_uint2(*(uint32_t*)&h0, *(uint32_t*)&h1);
    }
}

// ---------------------------------------------------------------------------
// transpose f32 -> f16: out[C][R] = (half)in[R][C]
// ---------------------------------------------------------------------------
__global__ __launch_bounds__(256)
void transpose_h(const float* __restrict__ in, __half* __restrict__ out, int R, int Cc) {
    __shared__ float t[32][33];
    const int c0 = blockIdx.x * 32, r0 = blockIdx.y * 32;
    const int tx = threadIdx.x, ty = threadIdx.y;
    #pragma unroll
    for (int i = ty; i < 32; i += 8)
        t[i][tx] = in[(size_t)(r0 + i) * Cc + c0 + tx];
    __syncthreads();
    #pragma unroll
    for (int i = ty; i < 32; i += 8)
        out[(size_t)(c0 + i) * R + r0 + tx] = __float2half(t[tx][i]);
}

// ---------------------------------------------------------------------------
// Scatter-add: out[dst] += (float)S[src] * w   (fp16 src, f32 RED atomics)
// ---------------------------------------------------------------------------
template<int D>
__global__ __launch_bounds__(256)
void scatter_add_h(const __half* __restrict__ S, const int* __restrict__ ei,
                   const float* __restrict__ ew, float* __restrict__ out) {
    constexpr int TPE = D / 4;        // threads per edge, 4 features each
    constexpr int EPB = 256 / TPE;
    const int e = blockIdx.x * EPB + threadIdx.x / TPE;
    if (e >= N_EDGES) return;
    const int j = threadIdx.x % TPE;
    const int src = ei[e];
    const int dst = ei[N_EDGES + e];
    const float w = ew[e];
    uint2 raw = ((const uint2*)(S + (size_t)src * D))[j];
    __half2 h0 = *(__half2*)&raw.x;
    __half2 h1 = *(__half2*)&raw.y;
    float2 f0 = __half22float2(h0);
    float2 f1 = __half22float2(h1);
    float4 v = make_float4(f0.x * w, f0.y * w, f1.x * w, f1.y * w);
    float* op = out + (size_t)dst * D + j * 4;
    asm volatile("red.global.add.v4.f32 [%0], {%1,%2,%3,%4};"
                 :: "l"(op), "f"(v.x), "f"(v.y), "f"(v.z), "f"(v.w) : "memory");
}

// ---------------------------------------------------------------------------
// bias+relu -> fp16 (feeds GEMM2)
// ---------------------------------------------------------------------------
template<int D>
__global__ void bias_relu_h(const float* __restrict__ p, const float* __restrict__ b,
                            uint2* __restrict__ out, int n4) {
    int i = blockIdx.x * blockDim.x + threadIdx.x;
    int stride = gridDim.x * blockDim.x;
    for (; i < n4; i += stride) {
        float4 v = ((const float4*)p)[i];
        float4 bb = ((const float4*)b)[i % (D / 4)];
        v.x = fmaxf(v.x + bb.x, 0.f);
        v.y = fmaxf(v.y + bb.y, 0.f);
        v.z = fmaxf(v.z + bb.z, 0.f);
        v.w = fmaxf(v.w + bb.w, 0.f);
        __half2 h0 = __floats2half2_rn(v.x, v.y);
        __half2 h1 = __floats2half2_rn(v.z, v.w);
        out[i] = make_uint2(*(uint32_t*)&h0, *(uint32_t*)&h1);
    }
}

// bias+relu in-place f32 (final output)
template<int D>
__global__ void bias_relu(float* __restrict__ p, const float* __restrict__ b, int n4) {
    int i = blockIdx.x * blockDim.x + threadIdx.x;
    int stride = gridDim.x * blockDim.x;
    for (; i < n4; i += stride) {
        float4 v = ((float4*)p)[i];
        float4 bb = ((const float4*)b)[i % (D / 4)];
        v.x = fmaxf(v.x + bb.x, 0.f);
        v.y = fmaxf(v.y + bb.y, 0.f);
        v.z = fmaxf(v.z + bb.z, 0.f);
        v.w = fmaxf(v.w + bb.w, 0.f);
        ((float4*)p)[i] = v;
    }
}

// ---------------------------------------------------------------------------
// launch
// ---------------------------------------------------------------------------
extern "C" void kernel_launch(void* const* d_in, const int* in_sizes, int n_in,
                              void* d_out, int out_size) {
    const float* x  = (const float*)d_in[0];
    const int*   ei = (const int*)  d_in[1];
    const float* ew = (const float*)d_in[2];
    const float* W1 = (const float*)d_in[3];
    const float* b1 = (const float*)d_in[4];
    const float* W2 = (const float*)d_in[5];
    const float* b2 = (const float*)d_in[6];
    float* out = (float*)d_out;

    float *h;
    __half *s1h, *s2h, *xh, *hh, *w1t, *w2t;
    cudaGetSymbolAddress((void**)&s1h, g_s1h);
    cudaGetSymbolAddress((void**)&h,   g_h);
    cudaGetSymbolAddress((void**)&s2h, g_s2h);
    cudaGetSymbolAddress((void**)&xh,  g_xh);
    cudaGetSymbolAddress((void**)&hh,  g_hh);
    cudaGetSymbolAddress((void**)&w1t, g_w1t);
    cudaGetSymbolAddress((void**)&w2t, g_w2t);

    static bool attr_set = false;
    if (!attr_set) {
        cudaFuncSetAttribute(gemm_h, cudaFuncAttributeMaxDynamicSharedMemorySize,
                             SMEM_BYTES);
        attr_set = true;
    }

    const int mblocks = (N_NODES + BM - 1) / BM;   // 391

    // fp16 staging
    to_half<<<4096, 256>>>((const float4*)x, (uint2*)xh, N_NODES * D_IN / 4);
    transpose_h<<<dim3(D_HID / 32, D_IN / 32), dim3(32, 8)>>>(W1, w1t, D_IN, D_HID);
    transpose_h<<<dim3(D_LAT / 32, D_HID / 32), dim3(32, 8)>>>(W2, w2t, D_HID, D_LAT);

    // Layer 1: s1h = x @ W1 ; h = scatter(s1h) ; hh = relu(h + b1) fp16
    gemm_h<<<dim3(mblocks, D_HID / BN), 512, SMEM_BYTES>>>(xh, w1t, s1h,
                                                           N_NODES, D_HID, D_IN);
    cudaMemsetAsync(h, 0, (size_t)N_NODES * D_HID * sizeof(float));
    scatter_add_h<D_HID><<<N_EDGES / (256 / (D_HID / 4)), 256>>>(s1h, ei, ew, h);
    bias_relu_h<D_HID><<<4096, 256>>>(h, b1, (uint2*)hh, N_NODES * D_HID / 4);

    // Layer 2: s2h = hh @ W2 ; out = relu(scatter(s2h) + b2)
    gemm_h<<<dim3(mblocks, D_LAT / BN), 512, SMEM_BYTES>>>(hh, w2t, s2h,
                                                           N_NODES, D_LAT, D_HID);
    cudaMemsetAsync(out, 0, (size_t)N_NODES * D_LAT * sizeof(float));
    scatter_add_h<D_LAT><<<N_EDGES / (256 / (D_LAT / 4)), 256>>>(s2h, ei, ew, out);
    bias_relu<D_LAT><<<4096, 256>>>(out, b2, N_NODES * D_LAT / 4);
}

// round 7
// speedup vs baseline: 1.5954x; 1.5288x over previous
#include <cuda_runtime.h>
#include <cuda_fp16.h>
#include <cstdint>

#define N_NODES 50000
#define N_EDGES 400000
#define D_IN    1024
#define D_HID   512
#define D_LAT   256

// Scratch (allocation-free rule: __device__ globals)
__device__ __half g_s1h[(size_t)N_NODES * D_HID];   // x @ W1 (fp16, gather src)
__device__ __half g_s2h[(size_t)N_NODES * D_LAT];   // hh @ W2 (fp16, gather src)
__device__ __half g_xh [(size_t)N_NODES * D_IN];    // x in fp16
__device__ __half g_hh [(size_t)N_NODES * D_HID];   // relu(agg1+b1) fp16
__device__ __half g_w1t[(size_t)D_HID * D_IN];      // W1^T fp16 [N][K]
__device__ __half g_w2t[(size_t)D_LAT * D_HID];     // W2^T fp16 [N][K]
// CSR-by-dst build
__device__ int   g_cnt [N_NODES];
__device__ int   g_off [N_NODES + 1];
__device__ int   g_cur [N_NODES];
__device__ int   g_psrc[N_EDGES];
__device__ float g_pw  [N_EDGES];

// ---------------------------------------------------------------------------
// fp16 mma.sync GEMM: C[M,N](f16) = A[M,K](f16) @ Bt[N,K](f16)^T
// CTA 128x256, BK=32, 3-stage cp.async, 512 thr (16 warps, 64x32 warp tile),
// ldmatrix.x4 fragment loads under XOR-16B swizzle.
// ---------------------------------------------------------------------------
#define BM 128
#define BN 256
#define BK 32
#define STAGES 3
#define A_WORDS (BM * 16)
#define B_WORDS (BN * 16)
#define STAGE_WORDS (A_WORDS + B_WORDS)
#define SMEM_BYTES (STAGES * STAGE_WORDS * 4)

__device__ __forceinline__ void hmma(float c[4], const uint32_t a[4],
                                     uint32_t b0, uint32_t b1) {
    asm volatile(
        "mma.sync.aligned.m16n8k16.row.col.f32.f16.f16.f32 "
        "{%0,%1,%2,%3}, {%4,%5,%6,%7}, {%8,%9}, {%0,%1,%2,%3};"
        : "+f"(c[0]), "+f"(c[1]), "+f"(c[2]), "+f"(c[3])
        : "r"(a[0]), "r"(a[1]), "r"(a[2]), "r"(a[3]), "r"(b0), "r"(b1));
}

__device__ __forceinline__ void ldsm4(uint32_t r[4], uint32_t addr) {
    asm volatile("ldmatrix.sync.aligned.m8n8.x4.shared.b16 {%0,%1,%2,%3}, [%4];"
                 : "=r"(r[0]), "=r"(r[1]), "=r"(r[2]), "=r"(r[3]) : "r"(addr));
}

__device__ __forceinline__ void cp16(uint32_t dst, const void* src, int sz) {
    asm volatile("cp.async.ca.shared.global [%0], [%1], 16, %2;\n"
                 :: "r"(dst), "l"(src), "r"(sz));
}
__device__ __forceinline__ void cp16u(uint32_t dst, const void* src) {
    asm volatile("cp.async.ca.shared.global [%0], [%1], 16;\n"
                 :: "r"(dst), "l"(src));
}

__global__ __launch_bounds__(512, 1)
void gemm_h(const __half* __restrict__ A, const __half* __restrict__ Bt,
            __half* __restrict__ C, int M, int N, int K) {
    extern __shared__ uint32_t smem[];
    const uint32_t sbase = (uint32_t)__cvta_generic_to_shared(smem);

    const int tid  = threadIdx.x;
    const int lane = tid & 31;
    const int wid  = tid >> 5;
    const int warp_m = wid & 1;
    const int warp_n = wid >> 1;
    const int qr = lane >> 2;
    const int qc = lane & 3;
    const int brow = blockIdx.x * BM;
    const int bcol = blockIdx.y * BN;

    const int laneA_row = lane & 15;
    const int laneA_h   = lane >> 4;
    const int laneB_row = (lane & 7) + ((lane >> 4) << 3);
    const int laneB_h   = (lane >> 3) & 1;
    const int rowA_base = warp_m * 64 + laneA_row;
    const int rowB_base = warp_n * 32 + laneB_row;

    float acc[4][4][4];
    #pragma unroll
    for (int i = 0; i < 4; i++)
        #pragma unroll
        for (int j = 0; j < 4; j++)
            #pragma unroll
            for (int k = 0; k < 4; k++) acc[i][j][k] = 0.f;

    auto load_stage = [&](int kt, int s) {
        const int kb = kt * BK;
        const uint32_t ab = sbase + (uint32_t)(s * STAGE_WORDS) * 4;
        const uint32_t bb = ab + A_WORDS * 4;
        {
            int r = tid >> 2, c4 = tid & 3;
            int gr = brow + r;
            uint32_t dst = ab + r * 64 + ((c4 ^ ((r >> 1) & 3)) << 4);
            cp16(dst, A + (size_t)gr * K + kb + c4 * 8, (gr < M) ? 16 : 0);
        }
        #pragma unroll
        for (int t = 0; t < 2; t++) {
            int idx = tid + t * 512;
            int r = idx >> 2, c4 = idx & 3;
            uint32_t dst = bb + r * 64 + ((c4 ^ ((r >> 1) & 3)) << 4);
            cp16u(dst, Bt + (size_t)(bcol + r) * K + kb + c4 * 8);
        }
    };

    const int nk = K / BK;
    #pragma unroll
    for (int i = 0; i < STAGES - 1; i++) {
        load_stage(i, i);
        asm volatile("cp.async.commit_group;\n");
    }

    for (int kt = 0; kt < nk; kt++) {
        asm volatile("cp.async.wait_group %0;\n" :: "n"(STAGES - 2));
        __syncthreads();

        if (kt + STAGES - 1 < nk) load_stage(kt + STAGES - 1, (kt + STAGES - 1) % STAGES);
        asm volatile("cp.async.commit_group;\n");

        const int s = kt % STAGES;
        const uint32_t Ab = sbase + (uint32_t)(s * STAGE_WORDS) * 4;
        const uint32_t Bb = Ab + A_WORDS * 4;

        #pragma unroll
        for (int ks = 0; ks < 2; ks++) {
            uint32_t a[4][4], b[2][4];
            #pragma unroll
            for (int mt = 0; mt < 4; mt++) {
                int row = rowA_base + mt * 16;
                uint32_t ad = Ab + row * 64 +
                    (((ks * 2 + laneA_h) ^ ((row >> 1) & 3)) << 4);
                ldsm4(a[mt], ad);
            }
            #pragma unroll
            for (int np = 0; np < 2; np++) {
                int row = rowB_base + np * 16;
                uint32_t bd = Bb + row * 64 +
                    (((ks * 2 + laneB_h) ^ ((row >> 1) & 3)) << 4);
                ldsm4(b[np], bd);
            }
            #pragma unroll
            for (int mt = 0; mt < 4; mt++)
                #pragma unroll
                for (int nt = 0; nt < 4; nt++)
                    hmma(acc[mt][nt], a[mt], b[nt >> 1][(nt & 1) * 2],
                                             b[nt >> 1][(nt & 1) * 2 + 1]);
        }
        __syncthreads();
    }

    #pragma unroll
    for (int mt = 0; mt < 4; mt++) {
        int r = brow + warp_m * 64 + mt * 16 + qr;
        #pragma unroll
        for (int nt = 0; nt < 4; nt++) {
            int c = bcol + warp_n * 32 + nt * 8 + qc * 2;
            if (r < M) {
                __half2 h = __floats2half2_rn(acc[mt][nt][0], acc[mt][nt][1]);
                *(__half2*)(C + (size_t)r * N + c) = h;
            }
            if (r + 8 < M) {
                __half2 h = __floats2half2_rn(acc[mt][nt][2], acc[mt][nt][3]);
                *(__half2*)(C + (size_t)(r + 8) * N + c) = h;
            }
        }
    }
}

// ---------------------------------------------------------------------------
// CSR-by-dst build: histogram -> scan -> permute
// ---------------------------------------------------------------------------
__global__ void hist_k(const int* __restrict__ ei, int* __restrict__ cnt) {
    int e = blockIdx.x * blockDim.x + threadIdx.x;
    if (e < N_EDGES) atomicAdd(&cnt[ei[N_EDGES + e]], 1);
}

__global__ __launch_bounds__(1024)
void scan_k(const int* __restrict__ cnt, int* __restrict__ off, int* __restrict__ cur) {
    __shared__ int sums[1024];
    const int t = threadIdx.x;
    const int CH = (N_NODES + 1023) / 1024;   // 49
    const int lo = t * CH;
    const int hi = min(lo + CH, N_NODES);
    int s = 0;
    for (int i = lo; i < hi; i++) s += cnt[i];
    sums[t] = s;
    __syncthreads();
    for (int d = 1; d < 1024; d <<= 1) {
        int v = (t >= d) ? sums[t - d] : 0;
        __syncthreads();
        sums[t] += v;
        __syncthreads();
    }
    int run = (t == 0) ? 0 : sums[t - 1];
    for (int i = lo; i < hi; i++) {
        off[i] = run; cur[i] = run;
        run += cnt[i];
    }
    if (t == 1023) off[N_NODES] = run;
}

__global__ void permute_k(const int* __restrict__ ei, const float* __restrict__ ew,
                          int* __restrict__ cur, int* __restrict__ psrc,
                          float* __restrict__ pw) {
    int e = blockIdx.x * blockDim.x + threadIdx.x;
    if (e >= N_EDGES) return;
    int dst = ei[N_EDGES + e];
    int pos = atomicAdd(&cur[dst], 1);
    psrc[pos] = ei[e];
    pw[pos]   = ew[e];
}

// ---------------------------------------------------------------------------
// Gather aggregation (warp per node), fused bias+relu.
// D=512 -> fp16 out (feeds GEMM2);  D=256 -> f32 out (final).
// ---------------------------------------------------------------------------
__global__ __launch_bounds__(256)
void agg512_h(const __half* __restrict__ S, const int* __restrict__ off,
              const int* __restrict__ psrc, const float* __restrict__ pw,
              const float* __restrict__ bias, __half* __restrict__ outh) {
    const int node = (blockIdx.x * blockDim.x + threadIdx.x) >> 5;
    const int lane = threadIdx.x & 31;
    if (node >= N_NODES) return;
    const int e0 = off[node], e1 = off[node + 1];

    float acc[16];
    #pragma unroll
    for (int i = 0; i < 16; i++) acc[i] = 0.f;

    for (int e = e0; e < e1; e++) {
        const int src = psrc[e];
        const float w = pw[e];
        const uint4* row = (const uint4*)(S + (size_t)src * D_HID);
        #pragma unroll
        for (int t = 0; t < 2; t++) {
            uint4 r = row[lane + t * 32];
            float2 f0 = __half22float2(*(__half2*)&r.x);
            float2 f1 = __half22float2(*(__half2*)&r.y);
            float2 f2 = __half22float2(*(__half2*)&r.z);
            float2 f3 = __half22float2(*(__half2*)&r.w);
            acc[t*8+0] += f0.x * w; acc[t*8+1] += f0.y * w;
            acc[t*8+2] += f1.x * w; acc[t*8+3] += f1.y * w;
            acc[t*8+4] += f2.x * w; acc[t*8+5] += f2.y * w;
            acc[t*8+6] += f3.x * w; acc[t*8+7] += f3.y * w;
        }
    }
    #pragma unroll
    for (int t = 0; t < 2; t++) {
        const int fb = (lane + t * 32) * 8;
        float4 b0 = *(const float4*)(bias + fb);
        float4 b1 = *(const float4*)(bias + fb + 4);
        __half2 h0 = __floats2half2_rn(fmaxf(acc[t*8+0]+b0.x,0.f), fmaxf(acc[t*8+1]+b0.y,0.f));
        __half2 h1 = __floats2half2_rn(fmaxf(acc[t*8+2]+b0.z,0.f), fmaxf(acc[t*8+3]+b0.w,0.f));
        __half2 h2 = __floats2half2_rn(fmaxf(acc[t*8+4]+b1.x,0.f), fmaxf(acc[t*8+5]+b1.y,0.f));
        __half2 h3 = __floats2half2_rn(fmaxf(acc[t*8+6]+b1.z,0.f), fmaxf(acc[t*8+7]+b1.w,0.f));
        uint4 o;
        o.x = *(uint32_t*)&h0; o.y = *(uint32_t*)&h1;
        o.z = *(uint32_t*)&h2; o.w = *(uint32_t*)&h3;
        *(uint4*)(outh + (size_t)node * D_HID + fb) = o;
    }
}

__global__ __launch_bounds__(256)
void agg256_f(const __half* __restrict__ S, const int* __restrict__ off,
              const int* __restrict__ psrc, const float* __restrict__ pw,
              const float* __restrict__ bias, float* __restrict__ outf) {
    const int node = (blockIdx.x * blockDim.x + threadIdx.x) >> 5;
    const int lane = threadIdx.x & 31;
    if (node >= N_NODES) return;
    const int e0 = off[node], e1 = off[node + 1];

    float acc[8];
    #pragma unroll
    for (int i = 0; i < 8; i++) acc[i] = 0.f;

    for (int e = e0; e < e1; e++) {
        const int src = psrc[e];
        const float w = pw[e];
        uint4 r = ((const uint4*)(S + (size_t)src * D_LAT))[lane];
        float2 f0 = __half22float2(*(__half2*)&r.x);
        float2 f1 = __half22float2(*(__half2*)&r.y);
        float2 f2 = __half22float2(*(__half2*)&r.z);
        float2 f3 = __half22float2(*(__half2*)&r.w);
        acc[0] += f0.x * w; acc[1] += f0.y * w;
        acc[2] += f1.x * w; acc[3] += f1.y * w;
        acc[4] += f2.x * w; acc[5] += f2.y * w;
        acc[6] += f3.x * w; acc[7] += f3.y * w;
    }
    const int fb = lane * 8;
    float4 b0 = *(const float4*)(bias + fb);
    float4 b1 = *(const float4*)(bias + fb + 4);
    float4 o0 = make_float4(fmaxf(acc[0]+b0.x,0.f), fmaxf(acc[1]+b0.y,0.f),
                            fmaxf(acc[2]+b0.z,0.f), fmaxf(acc[3]+b0.w,0.f));
    float4 o1 = make_float4(fmaxf(acc[4]+b1.x,0.f), fmaxf(acc[5]+b1.y,0.f),
                            fmaxf(acc[6]+b1.z,0.f), fmaxf(acc[7]+b1.w,0.f));
    float* op = outf + (size_t)node * D_LAT + fb;
    *(float4*)op       = o0;
    *(float4*)(op + 4) = o1;
}

// ---------------------------------------------------------------------------
// staging
// ---------------------------------------------------------------------------
__global__ void to_half(const float4* __restrict__ in, uint2* __restrict__ out, int n4) {
    int i = blockIdx.x * blockDim.x + threadIdx.x;
    int stride = gridDim.x * blockDim.x;
    for (; i < n4; i += stride) {
        float4 v = in[i];
        __half2 h0 = __floats2half2_rn(v.x, v.y);
        __half2 h1 = __floats2half2_rn(v.z, v.w);
        out[i] = make_uint2(*(uint32_t*)&h0, *(uint32_t*)&h1);
    }
}

__global__ __launch_bounds__(256)
void transpose_h(const float* __restrict__ in, __half* __restrict__ out, int R, int Cc) {
    __shared__ float t[32][33];
    const int c0 = blockIdx.x * 32, r0 = blockIdx.y * 32;
    const int tx = threadIdx.x, ty = threadIdx.y;
    #pragma unroll
    for (int i = ty; i < 32; i += 8)
        t[i][tx] = in[(size_t)(r0 + i) * Cc + c0 + tx];
    __syncthreads();
    #pragma unroll
    for (int i = ty; i < 32; i += 8)
        out[(size_t)(c0 + i) * R + r0 + tx] = __float2half(t[tx][i]);
}

// ---------------------------------------------------------------------------
// launch
// ---------------------------------------------------------------------------
extern "C" void kernel_launch(void* const* d_in, const int* in_sizes, int n_in,
                              void* d_out, int out_size) {
    const float* x  = (const float*)d_in[0];
    const int*   ei = (const int*)  d_in[1];
    const float* ew = (const float*)d_in[2];
    const float* W1 = (const float*)d_in[3];
    const float* b1 = (const float*)d_in[4];
    const float* W2 = (const float*)d_in[5];
    const float* b2 = (const float*)d_in[6];
    float* out = (float*)d_out;

    __half *s1h, *s2h, *xh, *hh, *w1t, *w2t;
    int *cnt, *off, *cur, *psrc;
    float *pw;
    cudaGetSymbolAddress((void**)&s1h,  g_s1h);
    cudaGetSymbolAddress((void**)&s2h,  g_s2h);
    cudaGetSymbolAddress((void**)&xh,   g_xh);
    cudaGetSymbolAddress((void**)&hh,   g_hh);
    cudaGetSymbolAddress((void**)&w1t,  g_w1t);
    cudaGetSymbolAddress((void**)&w2t,  g_w2t);
    cudaGetSymbolAddress((void**)&cnt,  g_cnt);
    cudaGetSymbolAddress((void**)&off,  g_off);
    cudaGetSymbolAddress((void**)&cur,  g_cur);
    cudaGetSymbolAddress((void**)&psrc, g_psrc);
    cudaGetSymbolAddress((void**)&pw,   g_pw);

    static bool attr_set = false;
    if (!attr_set) {
        cudaFuncSetAttribute(gemm_h, cudaFuncAttributeMaxDynamicSharedMemorySize,
                             SMEM_BYTES);
        attr_set = true;
    }

    const int mblocks = (N_NODES + BM - 1) / BM;   // 391
    const int agg_blocks = (N_NODES * 32 + 255) / 256;  // 6250

    // CSR build (overlappable with staging/GEMM1 by the GPU's async queue)
    cudaMemsetAsync(cnt, 0, N_NODES * sizeof(int));
    hist_k<<<(N_EDGES + 255) / 256, 256>>>(ei, cnt);
    scan_k<<<1, 1024>>>(cnt, off, cur);
    permute_k<<<(N_EDGES + 255) / 256, 256>>>(ei, ew, cur, psrc, pw);

    // fp16 staging
    to_half<<<4096, 256>>>((const float4*)x, (uint2*)xh, N_NODES * D_IN / 4);
    transpose_h<<<dim3(D_HID / 32, D_IN / 32), dim3(32, 8)>>>(W1, w1t, D_IN, D_HID);
    transpose_h<<<dim3(D_LAT / 32, D_HID / 32), dim3(32, 8)>>>(W2, w2t, D_HID, D_LAT);

    // Layer 1: s1h = x @ W1 ; hh = relu(gather(s1h) + b1)  (fp16)
    gemm_h<<<dim3(mblocks, D_HID / BN), 512, SMEM_BYTES>>>(xh, w1t, s1h,
                                                           N_NODES, D_HID, D_IN);
    agg512_h<<<agg_blocks, 256>>>(s1h, off, psrc, pw, b1, hh);

    // Layer 2: s2h = hh @ W2 ; out = relu(gather(s2h) + b2)  (f32)
    gemm_h<<<dim3(mblocks, D_LAT / BN), 512, SMEM_BYTES>>>(hh, w2t, s2h,
                                                           N_NODES, D_LAT, D_HID);
    agg256_f<<<agg_blocks, 256>>>(s2h, off, psrc, pw, b2, out);
}

// round 8
// speedup vs baseline: 1.7492x; 1.0965x over previous
#include <cuda_runtime.h>
#include <cuda_fp16.h>
#include <cstdint>

#define N_NODES 50000
#define N_EDGES 400000
#define D_IN    1024
#define D_HID   512
#define D_LAT   256

// Scratch (allocation-free rule: __device__ globals)
__device__ __half g_s1h[(size_t)N_NODES * D_HID];   // x @ W1 (fp16, gather src)
__device__ __half g_s2h[(size_t)N_NODES * D_LAT];   // hh @ W2 (fp16, gather src)
__device__ __half g_xh [(size_t)N_NODES * D_IN];    // x in fp16
__device__ __half g_hh [(size_t)N_NODES * D_HID];   // relu(agg1+b1) fp16
__device__ __half g_w1t[(size_t)D_HID * D_IN];      // W1^T fp16 [N][K]
__device__ __half g_w2t[(size_t)D_LAT * D_HID];     // W2^T fp16 [N][K]
// CSR-by-dst build
__device__ int   g_cnt [N_NODES];
__device__ int   g_off [N_NODES + 1];
__device__ int   g_cur [N_NODES];
__device__ int   g_psrc[N_EDGES];
__device__ float g_pw  [N_EDGES];

// ---------------------------------------------------------------------------
// fp16 mma.sync GEMM: C[M,N](f16) = A[M,K](f16) @ Bt[N,K](f16)^T
// CTA 128x256, BK=64 (128B rows), 3-stage cp.async, 512 thr (16 warps,
// 64x32 warp tile), ldmatrix.x4 under XOR swizzle chunk' = chunk ^ (row&7).
// One __syncthreads per k-tile.
// ---------------------------------------------------------------------------
#define BM 128
#define BN 256
#define BK 64
#define STAGES 3
#define A_BYTES (BM * 128)                 // 16384
#define B_BYTES (BN * 128)                 // 32768
#define STAGE_BYTES (A_BYTES + B_BYTES)    // 49152
#define SMEM_BYTES (STAGES * STAGE_BYTES)  // 147456

__device__ __forceinline__ void hmma(float c[4], const uint32_t a[4],
                                     uint32_t b0, uint32_t b1) {
    asm volatile(
        "mma.sync.aligned.m16n8k16.row.col.f32.f16.f16.f32 "
        "{%0,%1,%2,%3}, {%4,%5,%6,%7}, {%8,%9}, {%0,%1,%2,%3};"
        : "+f"(c[0]), "+f"(c[1]), "+f"(c[2]), "+f"(c[3])
        : "r"(a[0]), "r"(a[1]), "r"(a[2]), "r"(a[3]), "r"(b0), "r"(b1));
}

__device__ __forceinline__ void ldsm4(uint32_t r[4], uint32_t addr) {
    asm volatile("ldmatrix.sync.aligned.m8n8.x4.shared.b16 {%0,%1,%2,%3}, [%4];"
                 : "=r"(r[0]), "=r"(r[1]), "=r"(r[2]), "=r"(r[3]) : "r"(addr));
}

__device__ __forceinline__ void cp16(uint32_t dst, const void* src, int sz) {
    asm volatile("cp.async.ca.shared.global [%0], [%1], 16, %2;\n"
                 :: "r"(dst), "l"(src), "r"(sz));
}
__device__ __forceinline__ void cp16u(uint32_t dst, const void* src) {
    asm volatile("cp.async.ca.shared.global [%0], [%1], 16;\n"
                 :: "r"(dst), "l"(src));
}

__global__ __launch_bounds__(512, 1)
void gemm_h(const __half* __restrict__ A, const __half* __restrict__ Bt,
            __half* __restrict__ C, int M, int N, int K) {
    extern __shared__ uint32_t smem[];
    const uint32_t sbase = (uint32_t)__cvta_generic_to_shared(smem);

    const int tid  = threadIdx.x;
    const int lane = tid & 31;
    const int wid  = tid >> 5;
    const int warp_m = wid & 1;
    const int warp_n = wid >> 1;
    const int qr = lane >> 2;
    const int qc = lane & 3;
    const int brow = blockIdx.x * BM;
    const int bcol = blockIdx.y * BN;

    const int laneA_row = lane & 15;
    const int laneA_h   = lane >> 4;
    const int laneB_row = (lane & 7) + ((lane >> 4) << 3);
    const int laneB_h   = (lane >> 3) & 1;
    const int rowA_base = warp_m * 64 + laneA_row;
    const int rowB_base = warp_n * 32 + laneB_row;

    float acc[4][4][4];
    #pragma unroll
    for (int i = 0; i < 4; i++)
        #pragma unroll
        for (int j = 0; j < 4; j++)
            #pragma unroll
            for (int k = 0; k < 4; k++) acc[i][j][k] = 0.f;

    // stage loader: rows of 8 x 16B chunks; chunk' = chunk ^ (row & 7)
    auto load_stage = [&](int kt, int s) {
        const int kb = kt * BK;                          // in halfs
        const uint32_t ab = sbase + (uint32_t)s * STAGE_BYTES;
        const uint32_t bb = ab + A_BYTES;
        #pragma unroll
        for (int t = 0; t < 2; t++) {                    // A: 1024 chunks
            int idx = tid + t * 512;
            int r = idx >> 3, c = idx & 7;
            int gr = brow + r;
            uint32_t dst = ab + r * 128 + ((c ^ (r & 7)) << 4);
            cp16(dst, A + (size_t)gr * K + kb + c * 8, (gr < M) ? 16 : 0);
        }
        #pragma unroll
        for (int t = 0; t < 4; t++) {                    // B: 2048 chunks
            int idx = tid + t * 512;
            int r = idx >> 3, c = idx & 7;
            uint32_t dst = bb + r * 128 + ((c ^ (r & 7)) << 4);
            cp16u(dst, Bt + (size_t)(bcol + r) * K + kb + c * 8);
        }
    };

    const int nk = K / BK;
    #pragma unroll
    for (int i = 0; i < STAGES - 1; i++) {
        load_stage(i, i);
        asm volatile("cp.async.commit_group;\n");
    }

    for (int kt = 0; kt < nk; kt++) {
        asm volatile("cp.async.wait_group %0;\n" :: "n"(STAGES - 2));
        __syncthreads();

        if (kt + STAGES - 1 < nk) load_stage(kt + STAGES - 1, (kt + STAGES - 1) % STAGES);
        asm volatile("cp.async.commit_group;\n");

        const int s = kt % STAGES;
        const uint32_t Ab = sbase + (uint32_t)s * STAGE_BYTES;
        const uint32_t Bb = Ab + A_BYTES;

        #pragma unroll
        for (int ks = 0; ks < 4; ks++) {
            uint32_t a[4][4], b[2][4];
            #pragma unroll
            for (int mt = 0; mt < 4; mt++) {
                int row = rowA_base + mt * 16;
                int ch  = ks * 2 + laneA_h;
                ldsm4(a[mt], Ab + row * 128 + ((ch ^ (row & 7)) << 4));
            }
            #pragma unroll
            for (int np = 0; np < 2; np++) {
                int row = rowB_base + np * 16;
                int ch  = ks * 2 + laneB_h;
                ldsm4(b[np], Bb + row * 128 + ((ch ^ (row & 7)) << 4));
            }
            #pragma unroll
            for (int mt = 0; mt < 4; mt++)
                #pragma unroll
                for (int nt = 0; nt < 4; nt++)
                    hmma(acc[mt][nt], a[mt], b[nt >> 1][(nt & 1) * 2],
                                             b[nt >> 1][(nt & 1) * 2 + 1]);
        }
        // no trailing sync: next iteration's top barrier orders stage reuse
    }

    #pragma unroll
    for (int mt = 0; mt < 4; mt++) {
        int r = brow + warp_m * 64 + mt * 16 + qr;
        #pragma unroll
        for (int nt = 0; nt < 4; nt++) {
            int c = bcol + warp_n * 32 + nt * 8 + qc * 2;
            if (r < M) {
                __half2 h = __floats2half2_rn(acc[mt][nt][0], acc[mt][nt][1]);
                *(__half2*)(C + (size_t)r * N + c) = h;
            }
            if (r + 8 < M) {
                __half2 h = __floats2half2_rn(acc[mt][nt][2], acc[mt][nt][3]);
                *(__half2*)(C + (size_t)(r + 8) * N + c) = h;
            }
        }
    }
}

// ---------------------------------------------------------------------------
// CSR-by-dst build: histogram -> scan -> permute
// ---------------------------------------------------------------------------
__global__ void hist_k(const int* __restrict__ ei, int* __restrict__ cnt) {
    int e = blockIdx.x * blockDim.x + threadIdx.x;
    if (e < N_EDGES) atomicAdd(&cnt[ei[N_EDGES + e]], 1);
}

__global__ __launch_bounds__(1024)
void scan_k(const int* __restrict__ cnt, int* __restrict__ off, int* __restrict__ cur) {
    __shared__ int sums[1024];
    const int t = threadIdx.x;
    const int CH = (N_NODES + 1023) / 1024;   // 49
    const int lo = t * CH;
    const int hi = min(lo + CH, N_NODES);
    int s = 0;
    for (int i = lo; i < hi; i++) s += cnt[i];
    sums[t] = s;
    __syncthreads();
    for (int d = 1; d < 1024; d <<= 1) {
        int v = (t >= d) ? sums[t - d] : 0;
        __syncthreads();
        sums[t] += v;
        __syncthreads();
    }
    int run = (t == 0) ? 0 : sums[t - 1];
    for (int i = lo; i < hi; i++) {
        off[i] = run; cur[i] = run;
        run += cnt[i];
    }
    if (t == 1023) off[N_NODES] = run;
}

__global__ void permute_k(const int* __restrict__ ei, const float* __restrict__ ew,
                          int* __restrict__ cur, int* __restrict__ psrc,
                          float* __restrict__ pw) {
    int e = blockIdx.x * blockDim.x + threadIdx.x;
    if (e >= N_EDGES) return;
    int dst = ei[N_EDGES + e];
    int pos = atomicAdd(&cur[dst], 1);
    psrc[pos] = ei[e];
    pw[pos]   = ew[e];
}

// ---------------------------------------------------------------------------
// Gather aggregation (warp per node), 2-edge unrolled, fused bias+relu.
// ---------------------------------------------------------------------------
__device__ __forceinline__ void acc8(float* acc, uint4 r, float w) {
    float2 f0 = __half22float2(*(__half2*)&r.x);
    float2 f1 = __half22float2(*(__half2*)&r.y);
    float2 f2 = __half22float2(*(__half2*)&r.z);
    float2 f3 = __half22float2(*(__half2*)&r.w);
    acc[0] += f0.x * w; acc[1] += f0.y * w;
    acc[2] += f1.x * w; acc[3] += f1.y * w;
    acc[4] += f2.x * w; acc[5] += f2.y * w;
    acc[6] += f3.x * w; acc[7] += f3.y * w;
}

__global__ __launch_bounds__(256)
void agg512_h(const __half* __restrict__ S, const int* __restrict__ off,
              const int* __restrict__ psrc, const float* __restrict__ pw,
              const float* __restrict__ bias, __half* __restrict__ outh) {
    const int node = (blockIdx.x * blockDim.x + threadIdx.x) >> 5;
    const int lane = threadIdx.x & 31;
    if (node >= N_NODES) return;
    const int e0 = off[node], e1 = off[node + 1];

    float acc[16];
    #pragma unroll
    for (int i = 0; i < 16; i++) acc[i] = 0.f;

    int e = e0;
    for (; e + 2 <= e1; e += 2) {
        const int   s0 = psrc[e],   s1 = psrc[e + 1];
        const float w0 = pw[e],     w1 = pw[e + 1];
        const uint4* r0 = (const uint4*)(S + (size_t)s0 * D_HID);
        const uint4* r1 = (const uint4*)(S + (size_t)s1 * D_HID);
        uint4 x0 = r0[lane];
        uint4 x1 = r0[lane + 32];
        uint4 y0 = r1[lane];
        uint4 y1 = r1[lane + 32];
        acc8(acc,     x0, w0);
        acc8(acc + 8, x1, w0);
        acc8(acc,     y0, w1);
        acc8(acc + 8, y1, w1);
    }
    if (e < e1) {
        const int   s0 = psrc[e];
        const float w0 = pw[e];
        const uint4* r0 = (const uint4*)(S + (size_t)s0 * D_HID);
        uint4 x0 = r0[lane];
        uint4 x1 = r0[lane + 32];
        acc8(acc,     x0, w0);
        acc8(acc + 8, x1, w0);
    }

    #pragma unroll
    for (int t = 0; t < 2; t++) {
        const int fb = (lane + t * 32) * 8;
        float4 b0 = *(const float4*)(bias + fb);
        float4 b1 = *(const float4*)(bias + fb + 4);
        float* a = acc + t * 8;
        __half2 h0 = __floats2half2_rn(fmaxf(a[0]+b0.x,0.f), fmaxf(a[1]+b0.y,0.f));
        __half2 h1 = __floats2half2_rn(fmaxf(a[2]+b0.z,0.f), fmaxf(a[3]+b0.w,0.f));
        __half2 h2 = __floats2half2_rn(fmaxf(a[4]+b1.x,0.f), fmaxf(a[5]+b1.y,0.f));
        __half2 h3 = __floats2half2_rn(fmaxf(a[6]+b1.z,0.f), fmaxf(a[7]+b1.w,0.f));
        uint4 o;
        o.x = *(uint32_t*)&h0; o.y = *(uint32_t*)&h1;
        o.z = *(uint32_t*)&h2; o.w = *(uint32_t*)&h3;
        *(uint4*)(outh + (size_t)node * D_HID + fb) = o;
    }
}

__global__ __launch_bounds__(256)
void agg256_f(const __half* __restrict__ S, const int* __restrict__ off,
              const int* __restrict__ psrc, const float* __restrict__ pw,
              const float* __restrict__ bias, float* __restrict__ outf) {
    const int node = (blockIdx.x * blockDim.x + threadIdx.x) >> 5;
    const int lane = threadIdx.x & 31;
    if (node >= N_NODES) return;
    const int e0 = off[node], e1 = off[node + 1];

    float acc[8];
    #pragma unroll
    for (int i = 0; i < 8; i++) acc[i] = 0.f;

    int e = e0;
    for (; e + 2 <= e1; e += 2) {
        const int   s0 = psrc[e],   s1 = psrc[e + 1];
        const float w0 = pw[e],     w1 = pw[e + 1];
        uint4 x = ((const uint4*)(S + (size_t)s0 * D_LAT))[lane];
        uint4 y = ((const uint4*)(S + (size_t)s1 * D_LAT))[lane];
        acc8(acc, x, w0);
        acc8(acc, y, w1);
    }
    if (e < e1) {
        uint4 x = ((const uint4*)(S + (size_t)psrc[e] * D_LAT))[lane];
        acc8(acc, x, pw[e]);
    }

    const int fb = lane * 8;
    float4 b0 = *(const float4*)(bias + fb);
    float4 b1 = *(const float4*)(bias + fb + 4);
    float4 o0 = make_float4(fmaxf(acc[0]+b0.x,0.f), fmaxf(acc[1]+b0.y,0.f),
                            fmaxf(acc[2]+b0.z,0.f), fmaxf(acc[3]+b0.w,0.f));
    float4 o1 = make_float4(fmaxf(acc[4]+b1.x,0.f), fmaxf(acc[5]+b1.y,0.f),
                            fmaxf(acc[6]+b1.z,0.f), fmaxf(acc[7]+b1.w,0.f));
    float* op = outf + (size_t)node * D_LAT + fb;
    *(float4*)op       = o0;
    *(float4*)(op + 4) = o1;
}

// ---------------------------------------------------------------------------
// staging
// ---------------------------------------------------------------------------
__global__ void to_half(const float4* __restrict__ in, uint2* __restrict__ out, int n4) {
    int i = blockIdx.x * blockDim.x + threadIdx.x;
    int stride = gridDim.x * blockDim.x;
    for (; i < n4; i += stride) {
        float4 v = in[i];
        __half2 h0 = __floats2half2_rn(v.x, v.y);
        __half2 h1 = __floats2half2_rn(v.z, v.w);
        out[i] = make_uint2(*(uint32_t*)&h0, *(uint32_t*)&h1);
    }
}

__global__ __launch_bounds__(256)
void transpose_h(const float* __restrict__ in, __half* __restrict__ out, int R, int Cc) {
    __shared__ float t[32][33];
    const int c0 = blockIdx.x * 32, r0 = blockIdx.y * 32;
    const int tx = threadIdx.x, ty = threadIdx.y;
    #pragma unroll
    for (int i = ty; i < 32; i += 8)
        t[i][tx] = in[(size_t)(r0 + i) * Cc + c0 + tx];
    __syncthreads();
    #pragma unroll
    for (int i = ty; i < 32; i += 8)
        out[(size_t)(c0 + i) * R + r0 + tx] = __float2half(t[tx][i]);
}

// ---------------------------------------------------------------------------
// launch
// ---------------------------------------------------------------------------
extern "C" void kernel_launch(void* const* d_in, const int* in_sizes, int n_in,
                              void* d_out, int out_size) {
    const float* x  = (const float*)d_in[0];
    const int*   ei = (const int*)  d_in[1];
    const float* ew = (const float*)d_in[2];
    const float* W1 = (const float*)d_in[3];
    const float* b1 = (const float*)d_in[4];
    const float* W2 = (const float*)d_in[5];
    const float* b2 = (const float*)d_in[6];
    float* out = (float*)d_out;

    __half *s1h, *s2h, *xh, *hh, *w1t, *w2t;
    int *cnt, *off, *cur, *psrc;
    float *pw;
    cudaGetSymbolAddress((void**)&s1h,  g_s1h);
    cudaGetSymbolAddress((void**)&s2h,  g_s2h);
    cudaGetSymbolAddress((void**)&xh,   g_xh);
    cudaGetSymbolAddress((void**)&hh,   g_hh);
    cudaGetSymbolAddress((void**)&w1t,  g_w1t);
    cudaGetSymbolAddress((void**)&w2t,  g_w2t);
    cudaGetSymbolAddress((void**)&cnt,  g_cnt);
    cudaGetSymbolAddress((void**)&off,  g_off);
    cudaGetSymbolAddress((void**)&cur,  g_cur);
    cudaGetSymbolAddress((void**)&psrc, g_psrc);
    cudaGetSymbolAddress((void**)&pw,   g_pw);

    static bool attr_set = false;
    if (!attr_set) {
        cudaFuncSetAttribute(gemm_h, cudaFuncAttributeMaxDynamicSharedMemorySize,
                             SMEM_BYTES);
        attr_set = true;
    }

    const int mblocks = (N_NODES + BM - 1) / BM;        // 391
    const int agg_blocks = (N_NODES * 32 + 255) / 256;  // 6250

    // CSR build
    cudaMemsetAsync(cnt, 0, N_NODES * sizeof(int));
    hist_k<<<(N_EDGES + 255) / 256, 256>>>(ei, cnt);
    scan_k<<<1, 1024>>>(cnt, off, cur);
    permute_k<<<(N_EDGES + 255) / 256, 256>>>(ei, ew, cur, psrc, pw);

    // fp16 staging
    to_half<<<4096, 256>>>((const float4*)x, (uint2*)xh, N_NODES * D_IN / 4);
    transpose_h<<<dim3(D_HID / 32, D_IN / 32), dim3(32, 8)>>>(W1, w1t, D_IN, D_HID);
    transpose_h<<<dim3(D_LAT / 32, D_HID / 32), dim3(32, 8)>>>(W2, w2t, D_HID, D_LAT);

    // Layer 1: s1h = x @ W1 ; hh = relu(gather(s1h) + b1)  (fp16)
    gemm_h<<<dim3(mblocks, D_HID / BN), 512, SMEM_BYTES>>>(xh, w1t, s1h,
                                                           N_NODES, D_HID, D_IN);
    agg512_h<<<agg_blocks, 256>>>(s1h, off, psrc, pw, b1, hh);

    // Layer 2: s2h = hh @ W2 ; out = relu(gather(s2h) + b2)  (f32)
    gemm_h<<<dim3(mblocks, D_LAT / BN), 512, SMEM_BYTES>>>(hh, w2t, s2h,
                                                           N_NODES, D_LAT, D_HID);
    agg256_f<<<agg_blocks, 256>>>(s2h, off, psrc, pw, b2, out);
}

// round 9
// speedup vs baseline: 2.1451x; 1.2263x over previous
#include <cuda_runtime.h>
#include <cuda_fp16.h>
#include <cstdint>

#define N_NODES 50000
#define N_EDGES 400000
#define D_IN    1024
#define D_HID   512
#define D_LAT   256

// Scratch (allocation-free rule: __device__ globals)
__device__ __half g_s1h[(size_t)N_NODES * D_HID];   // x @ W1 (fp16, gather src)
__device__ __half g_s2h[(size_t)N_NODES * D_LAT];   // hh @ W2 (fp16, gather src)
__device__ __half g_xh [(size_t)N_NODES * D_IN];    // x in fp16
__device__ __half g_hh [(size_t)N_NODES * D_HID];   // relu(agg1+b1) fp16
__device__ __half g_w1t[(size_t)D_HID * D_IN];      // W1^T fp16 [N][K]
__device__ __half g_w2t[(size_t)D_LAT * D_HID];     // W2^T fp16 [N][K]
// CSR-by-dst build
__device__ int   g_cnt [N_NODES];
__device__ int   g_off [N_NODES + 1];
__device__ int   g_cur [N_NODES];
__device__ int   g_psrc[N_EDGES];
__device__ float g_pw  [N_EDGES];

// ---------------------------------------------------------------------------
// fp16 mma.sync GEMM (unchanged from R8): CTA 128x256, BK=64, 3-stage,
// 512 thr, 64x32 warp tile, ldmatrix.x4, XOR swizzle chunk' = chunk ^ (row&7)
// ---------------------------------------------------------------------------
#define BM 128
#define BN 256
#define BK 64
#define STAGES 3
#define A_BYTES (BM * 128)
#define B_BYTES (BN * 128)
#define STAGE_BYTES (A_BYTES + B_BYTES)
#define SMEM_BYTES (STAGES * STAGE_BYTES)

__device__ __forceinline__ void hmma(float c[4], const uint32_t a[4],
                                     uint32_t b0, uint32_t b1) {
    asm volatile(
        "mma.sync.aligned.m16n8k16.row.col.f32.f16.f16.f32 "
        "{%0,%1,%2,%3}, {%4,%5,%6,%7}, {%8,%9}, {%0,%1,%2,%3};"
        : "+f"(c[0]), "+f"(c[1]), "+f"(c[2]), "+f"(c[3])
        : "r"(a[0]), "r"(a[1]), "r"(a[2]), "r"(a[3]), "r"(b0), "r"(b1));
}

__device__ __forceinline__ void ldsm4(uint32_t r[4], uint32_t addr) {
    asm volatile("ldmatrix.sync.aligned.m8n8.x4.shared.b16 {%0,%1,%2,%3}, [%4];"
                 : "=r"(r[0]), "=r"(r[1]), "=r"(r[2]), "=r"(r[3]) : "r"(addr));
}

__device__ __forceinline__ void cp16(uint32_t dst, const void* src, int sz) {
    asm volatile("cp.async.ca.shared.global [%0], [%1], 16, %2;\n"
                 :: "r"(dst), "l"(src), "r"(sz));
}
__device__ __forceinline__ void cp16u(uint32_t dst, const void* src) {
    asm volatile("cp.async.ca.shared.global [%0], [%1], 16;\n"
                 :: "r"(dst), "l"(src));
}

__global__ __launch_bounds__(512, 1)
void gemm_h(const __half* __restrict__ A, const __half* __restrict__ Bt,
            __half* __restrict__ C, int M, int N, int K) {
    extern __shared__ uint32_t smem[];
    const uint32_t sbase = (uint32_t)__cvta_generic_to_shared(smem);

    const int tid  = threadIdx.x;
    const int lane = tid & 31;
    const int wid  = tid >> 5;
    const int warp_m = wid & 1;
    const int warp_n = wid >> 1;
    const int qr = lane >> 2;
    const int qc = lane & 3;
    const int brow = blockIdx.x * BM;
    const int bcol = blockIdx.y * BN;

    const int laneA_row = lane & 15;
    const int laneA_h   = lane >> 4;
    const int laneB_row = (lane & 7) + ((lane >> 4) << 3);
    const int laneB_h   = (lane >> 3) & 1;
    const int rowA_base = warp_m * 64 + laneA_row;
    const int rowB_base = warp_n * 32 + laneB_row;

    float acc[4][4][4];
    #pragma unroll
    for (int i = 0; i < 4; i++)
        #pragma unroll
        for (int j = 0; j < 4; j++)
            #pragma unroll
            for (int k = 0; k < 4; k++) acc[i][j][k] = 0.f;

    auto load_stage = [&](int kt, int s) {
        const int kb = kt * BK;
        const uint32_t ab = sbase + (uint32_t)s * STAGE_BYTES;
        const uint32_t bb = ab + A_BYTES;
        #pragma unroll
        for (int t = 0; t < 2; t++) {
            int idx = tid + t * 512;
            int r = idx >> 3, c = idx & 7;
            int gr = brow + r;
            uint32_t dst = ab + r * 128 + ((c ^ (r & 7)) << 4);
            cp16(dst, A + (size_t)gr * K + kb + c * 8, (gr < M) ? 16 : 0);
        }
        #pragma unroll
        for (int t = 0; t < 4; t++) {
            int idx = tid + t * 512;
            int r = idx >> 3, c = idx & 7;
            uint32_t dst = bb + r * 128 + ((c ^ (r & 7)) << 4);
            cp16u(dst, Bt + (size_t)(bcol + r) * K + kb + c * 8);
        }
    };

    const int nk = K / BK;
    #pragma unroll
    for (int i = 0; i < STAGES - 1; i++) {
        load_stage(i, i);
        asm volatile("cp.async.commit_group;\n");
    }

    for (int kt = 0; kt < nk; kt++) {
        asm volatile("cp.async.wait_group %0;\n" :: "n"(STAGES - 2));
        __syncthreads();

        if (kt + STAGES - 1 < nk) load_stage(kt + STAGES - 1, (kt + STAGES - 1) % STAGES);
        asm volatile("cp.async.commit_group;\n");

        const int s = kt % STAGES;
        const uint32_t Ab = sbase + (uint32_t)s * STAGE_BYTES;
        const uint32_t Bb = Ab + A_BYTES;

        #pragma unroll
        for (int ks = 0; ks < 4; ks++) {
            uint32_t a[4][4], b[2][4];
            #pragma unroll
            for (int mt = 0; mt < 4; mt++) {
                int row = rowA_base + mt * 16;
                int ch  = ks * 2 + laneA_h;
                ldsm4(a[mt], Ab + row * 128 + ((ch ^ (row & 7)) << 4));
            }
            #pragma unroll
            for (int np = 0; np < 2; np++) {
                int row = rowB_base + np * 16;
                int ch  = ks * 2 + laneB_h;
                ldsm4(b[np], Bb + row * 128 + ((ch ^ (row & 7)) << 4));
            }
            #pragma unroll
            for (int mt = 0; mt < 4; mt++)
                #pragma unroll
                for (int nt = 0; nt < 4; nt++)
                    hmma(acc[mt][nt], a[mt], b[nt >> 1][(nt & 1) * 2],
                                             b[nt >> 1][(nt & 1) * 2 + 1]);
        }
    }

    #pragma unroll
    for (int mt = 0; mt < 4; mt++) {
        int r = brow + warp_m * 64 + mt * 16 + qr;
        #pragma unroll
        for (int nt = 0; nt < 4; nt++) {
            int c = bcol + warp_n * 32 + nt * 8 + qc * 2;
            if (r < M) {
                __half2 h = __floats2half2_rn(acc[mt][nt][0], acc[mt][nt][1]);
                *(__half2*)(C + (size_t)r * N + c) = h;
            }
            if (r + 8 < M) {
                __half2 h = __floats2half2_rn(acc[mt][nt][2], acc[mt][nt][3]);
                *(__half2*)(C + (size_t)(r + 8) * N + c) = h;
            }
        }
    }
}

// ---------------------------------------------------------------------------
// CSR-by-dst build: histogram -> scan -> permute
// ---------------------------------------------------------------------------
__global__ void hist_k(const int* __restrict__ ei, int* __restrict__ cnt) {
    int e = blockIdx.x * blockDim.x + threadIdx.x;
    if (e < N_EDGES) atomicAdd(&cnt[ei[N_EDGES + e]], 1);
}

__global__ __launch_bounds__(1024)
void scan_k(const int* __restrict__ cnt, int* __restrict__ off, int* __restrict__ cur) {
    __shared__ int sums[1024];
    const int t = threadIdx.x;
    const int CH = (N_NODES + 1023) / 1024;   // 49
    const int lo = t * CH;
    const int hi = min(lo + CH, N_NODES);
    int s = 0;
    for (int i = lo; i < hi; i++) s += cnt[i];
    sums[t] = s;
    __syncthreads();
    for (int d = 1; d < 1024; d <<= 1) {
        int v = (t >= d) ? sums[t - d] : 0;
        __syncthreads();
        sums[t] += v;
        __syncthreads();
    }
    int run = (t == 0) ? 0 : sums[t - 1];
    for (int i = lo; i < hi; i++) {
        off[i] = run; cur[i] = run;
        run += cnt[i];
    }
    if (t == 1023) off[N_NODES] = run;
}

__global__ void permute_k(const int* __restrict__ ei, const float* __restrict__ ew,
                          int* __restrict__ cur, int* __restrict__ psrc,
                          float* __restrict__ pw) {
    int e = blockIdx.x * blockDim.x + threadIdx.x;
    if (e >= N_EDGES) return;
    int dst = ei[N_EDGES + e];
    int pos = atomicAdd(&cur[dst], 1);
    psrc[pos] = ei[e];
    pw[pos]   = ew[e];
}

// ---------------------------------------------------------------------------
// Gather aggregation (warp per node), 4-edge unrolled, fused bias+relu.
// ---------------------------------------------------------------------------
__device__ __forceinline__ void acc8(float* acc, uint4 r, float w) {
    float2 f0 = __half22float2(*(__half2*)&r.x);
    float2 f1 = __half22float2(*(__half2*)&r.y);
    float2 f2 = __half22float2(*(__half2*)&r.z);
    float2 f3 = __half22float2(*(__half2*)&r.w);
    acc[0] += f0.x * w; acc[1] += f0.y * w;
    acc[2] += f1.x * w; acc[3] += f1.y * w;
    acc[4] += f2.x * w; acc[5] += f2.y * w;
    acc[6] += f3.x * w; acc[7] += f3.y * w;
}

__global__ __launch_bounds__(256)
void agg512_h(const __half* __restrict__ S, const int* __restrict__ off,
              const int* __restrict__ psrc, const float* __restrict__ pw,
              const float* __restrict__ bias, __half* __restrict__ outh) {
    const int node = (blockIdx.x * blockDim.x + threadIdx.x) >> 5;
    const int lane = threadIdx.x & 31;
    if (node >= N_NODES) return;
    const int e0 = off[node], e1 = off[node + 1];

    float acc[16];
    #pragma unroll
    for (int i = 0; i < 16; i++) acc[i] = 0.f;

    int e = e0;
    for (; e + 4 <= e1; e += 4) {
        int   s0 = psrc[e],   s1 = psrc[e+1], s2 = psrc[e+2], s3 = psrc[e+3];
        float w0 = pw[e],     w1 = pw[e+1],   w2 = pw[e+2],   w3 = pw[e+3];
        const uint4* r0 = (const uint4*)(S + (size_t)s0 * D_HID);
        const uint4* r1 = (const uint4*)(S + (size_t)s1 * D_HID);
        const uint4* r2 = (const uint4*)(S + (size_t)s2 * D_HID);
        const uint4* r3 = (const uint4*)(S + (size_t)s3 * D_HID);
        uint4 x0 = r0[lane],      y0 = r1[lane],      z0 = r2[lane],      u0 = r3[lane];
        uint4 x1 = r0[lane + 32], y1 = r1[lane + 32], z1 = r2[lane + 32], u1 = r3[lane + 32];
        acc8(acc, x0, w0); acc8(acc + 8, x1, w0);
        acc8(acc, y0, w1); acc8(acc + 8, y1, w1);
        acc8(acc, z0, w2); acc8(acc + 8, z1, w2);
        acc8(acc, u0, w3); acc8(acc + 8, u1, w3);
    }
    for (; e < e1; e++) {
        int s0 = psrc[e]; float w0 = pw[e];
        const uint4* r0 = (const uint4*)(S + (size_t)s0 * D_HID);
        uint4 x0 = r0[lane];
        uint4 x1 = r0[lane + 32];
        acc8(acc, x0, w0); acc8(acc + 8, x1, w0);
    }

    #pragma unroll
    for (int t = 0; t < 2; t++) {
        const int fb = (lane + t * 32) * 8;
        float4 b0 = *(const float4*)(bias + fb);
        float4 b1 = *(const float4*)(bias + fb + 4);
        float* a = acc + t * 8;
        __half2 h0 = __floats2half2_rn(fmaxf(a[0]+b0.x,0.f), fmaxf(a[1]+b0.y,0.f));
        __half2 h1 = __floats2half2_rn(fmaxf(a[2]+b0.z,0.f), fmaxf(a[3]+b0.w,0.f));
        __half2 h2 = __floats2half2_rn(fmaxf(a[4]+b1.x,0.f), fmaxf(a[5]+b1.y,0.f));
        __half2 h3 = __floats2half2_rn(fmaxf(a[6]+b1.z,0.f), fmaxf(a[7]+b1.w,0.f));
        uint4 o;
        o.x = *(uint32_t*)&h0; o.y = *(uint32_t*)&h1;
        o.z = *(uint32_t*)&h2; o.w = *(uint32_t*)&h3;
        *(uint4*)(outh + (size_t)node * D_HID + fb) = o;
    }
}

__global__ __launch_bounds__(256)
void agg256_f(const __half* __restrict__ S, const int* __restrict__ off,
              const int* __restrict__ psrc, const float* __restrict__ pw,
              const float* __restrict__ bias, float* __restrict__ outf) {
    const int node = (blockIdx.x * blockDim.x + threadIdx.x) >> 5;
    const int lane = threadIdx.x & 31;
    if (node >= N_NODES) return;
    const int e0 = off[node], e1 = off[node + 1];

    float acc[8];
    #pragma unroll
    for (int i = 0; i < 8; i++) acc[i] = 0.f;

    int e = e0;
    for (; e + 4 <= e1; e += 4) {
        int   s0 = psrc[e],   s1 = psrc[e+1], s2 = psrc[e+2], s3 = psrc[e+3];
        float w0 = pw[e],     w1 = pw[e+1],   w2 = pw[e+2],   w3 = pw[e+3];
        uint4 x = ((const uint4*)(S + (size_t)s0 * D_LAT))[lane];
        uint4 y = ((const uint4*)(S + (size_t)s1 * D_LAT))[lane];
        uint4 z = ((const uint4*)(S + (size_t)s2 * D_LAT))[lane];
        uint4 u = ((const uint4*)(S + (size_t)s3 * D_LAT))[lane];
        acc8(acc, x, w0); acc8(acc, y, w1); acc8(acc, z, w2); acc8(acc, u, w3);
    }
    for (; e < e1; e++) {
        uint4 x = ((const uint4*)(S + (size_t)psrc[e] * D_LAT))[lane];
        acc8(acc, x, pw[e]);
    }

    const int fb = lane * 8;
    float4 b0 = *(const float4*)(bias + fb);
    float4 b1 = *(const float4*)(bias + fb + 4);
    float4 o0 = make_float4(fmaxf(acc[0]+b0.x,0.f), fmaxf(acc[1]+b0.y,0.f),
                            fmaxf(acc[2]+b0.z,0.f), fmaxf(acc[3]+b0.w,0.f));
    float4 o1 = make_float4(fmaxf(acc[4]+b1.x,0.f), fmaxf(acc[5]+b1.y,0.f),
                            fmaxf(acc[6]+b1.z,0.f), fmaxf(acc[7]+b1.w,0.f));
    float* op = outf + (size_t)node * D_LAT + fb;
    *(float4*)op       = o0;
    *(float4*)(op + 4) = o1;
}

// ---------------------------------------------------------------------------
// staging
// ---------------------------------------------------------------------------
__global__ void to_half(const float4* __restrict__ in, uint2* __restrict__ out, int n4) {
    int i = blockIdx.x * blockDim.x + threadIdx.x;
    int stride = gridDim.x * blockDim.x;
    for (; i < n4; i += stride) {
        float4 v = in[i];
        __half2 h0 = __floats2half2_rn(v.x, v.y);
        __half2 h1 = __floats2half2_rn(v.z, v.w);
        out[i] = make_uint2(*(uint32_t*)&h0, *(uint32_t*)&h1);
    }
}

__global__ __launch_bounds__(256)
void transpose_h(const float* __restrict__ in, __half* __restrict__ out, int R, int Cc) {
    __shared__ float t[32][33];
    const int c0 = blockIdx.x * 32, r0 = blockIdx.y * 32;
    const int tx = threadIdx.x, ty = threadIdx.y;
    #pragma unroll
    for (int i = ty; i < 32; i += 8)
        t[i][tx] = in[(size_t)(r0 + i) * Cc + c0 + tx];
    __syncthreads();
    #pragma unroll
    for (int i = ty; i < 32; i += 8)
        out[(size_t)(c0 + i) * R + r0 + tx] = __float2half(t[tx][i]);
}

// ---------------------------------------------------------------------------
// launch — forked-stream graph: CSR branch runs concurrently with GEMM1 chain
// ---------------------------------------------------------------------------
extern "C" void kernel_launch(void* const* d_in, const int* in_sizes, int n_in,
                              void* d_out, int out_size) {
    const float* x  = (const float*)d_in[0];
    const int*   ei = (const int*)  d_in[1];
    const float* ew = (const float*)d_in[2];
    const float* W1 = (const float*)d_in[3];
    const float* b1 = (const float*)d_in[4];
    const float* W2 = (const float*)d_in[5];
    const float* b2 = (const float*)d_in[6];
    float* out = (float*)d_out;

    __half *s1h, *s2h, *xh, *hh, *w1t, *w2t;
    int *cnt, *off, *cur, *psrc;
    float *pw;
    cudaGetSymbolAddress((void**)&s1h,  g_s1h);
    cudaGetSymbolAddress((void**)&s2h,  g_s2h);
    cudaGetSymbolAddress((void**)&xh,   g_xh);
    cudaGetSymbolAddress((void**)&hh,   g_hh);
    cudaGetSymbolAddress((void**)&w1t,  g_w1t);
    cudaGetSymbolAddress((void**)&w2t,  g_w2t);
    cudaGetSymbolAddress((void**)&cnt,  g_cnt);
    cudaGetSymbolAddress((void**)&off,  g_off);
    cudaGetSymbolAddress((void**)&cur,  g_cur);
    cudaGetSymbolAddress((void**)&psrc, g_psrc);
    cudaGetSymbolAddress((void**)&pw,   g_pw);

    static cudaStream_t s2 = nullptr;
    static cudaEvent_t evA = nullptr, evB = nullptr;
    static bool init_done = false;
    if (!init_done) {
        cudaFuncSetAttribute(gemm_h, cudaFuncAttributeMaxDynamicSharedMemorySize,
                             SMEM_BYTES);
        cudaStreamCreateWithFlags(&s2, cudaStreamNonBlocking);
        cudaEventCreateWithFlags(&evA, cudaEventDisableTiming);
        cudaEventCreateWithFlags(&evB, cudaEventDisableTiming);
        init_done = true;
    }

    const int mblocks = (N_NODES + BM - 1) / BM;        // 391
    const int agg_blocks = (N_NODES * 32 + 255) / 256;  // 6250

    // fork: side branch (CSR build + W2 transpose) on s2
    cudaEventRecord(evA, 0);
    cudaStreamWaitEvent(s2, evA, 0);
    cudaMemsetAsync(cnt, 0, N_NODES * sizeof(int), s2);
    hist_k<<<(N_EDGES + 255) / 256, 256, 0, s2>>>(ei, cnt);
    scan_k<<<1, 1024, 0, s2>>>(cnt, off, cur);
    permute_k<<<(N_EDGES + 255) / 256, 256, 0, s2>>>(ei, ew, cur, psrc, pw);
    transpose_h<<<dim3(D_LAT / 32, D_HID / 32), dim3(32, 8), 0, s2>>>(W2, w2t,
                                                                      D_HID, D_LAT);
    cudaEventRecord(evB, s2);

    // main branch: staging + GEMM1
    to_half<<<4096, 256>>>((const float4*)x, (uint2*)xh, N_NODES * D_IN / 4);
    transpose_h<<<dim3(D_HID / 32, D_IN / 32), dim3(32, 8)>>>(W1, w1t, D_IN, D_HID);
    gemm_h<<<dim3(mblocks, D_HID / BN), 512, SMEM_BYTES>>>(xh, w1t, s1h,
                                                           N_NODES, D_HID, D_IN);

    // join: agg needs CSR arrays
    cudaStreamWaitEvent(0, evB, 0);
    agg512_h<<<agg_blocks, 256>>>(s1h, off, psrc, pw, b1, hh);

    // Layer 2
    gemm_h<<<dim3(mblocks, D_LAT / BN), 512, SMEM_BYTES>>>(hh, w2t, s2h,
                                                           N_NODES, D_LAT, D_HID);
    agg256_f<<<agg_blocks, 256>>>(s2h, off, psrc, pw, b2, out);
}